// round 17
// baseline (speedup 1.0000x reference)
#include <cuda_runtime.h>
#include <cstdint>

// ---------------------------------------------------------------------------
// StochLinear v14: exact JAX threefry bits -> bit-packed CSA-popcount GEMM.
//   out[b,n] = 0.5*S - 0.25*(sA[b]+sB[n]) + 2048 + bias[n]      (exact fp32)
// v14 = v13 with a widened epilogue (8 cols/thread, uint4 short loads,
// 2x float4 stores) -- GEMM (94% of alu/xu dual-pipe floor) and bitgen
// (90% of its alu floor) unchanged.
// ---------------------------------------------------------------------------

#define B_DIM 4096
#define K_DIM 2048
#define N_DIM 2048
#define ROW_WORDS 512              // 8 l-slices * 64 words
#define CW   32                    // words per k-chunk (128 B)
#define NCH  (ROW_WORDS / CW)      // 16 total; 8 per split
#define KSPLIT 2
#define NCHS (NCH / KSPLIT)        // 8
#define PITCH 144                  // 128 B row + 16 B pad
#define BM 128
#define BN 64
#define A_TILE_B (BM * PITCH)      // 18432
#define B_TILE_B (BN * PITCH)      // 9216
#define STAGE_B  (A_TILE_B + B_TILE_B)  // 27648
#define NSTG 4
#define SMEM_BYTES (NSTG * STAGE_B)     // 110592

__device__ uint32_t g_Apack[(size_t)B_DIM * ROW_WORDS]; // 8 MB
__device__ uint32_t g_Wpack[(size_t)N_DIM * ROW_WORDS]; // 4 MB
__device__ int g_sA[B_DIM];
__device__ int g_sB[N_DIM];
__device__ short g_Sp[KSPLIT][(size_t)B_DIM * N_DIM];   // 32 MB partials (i16)

#ifdef __CUDA_ARCH__
#define ROTL(x, r) __funnelshift_l((x), (x), (r))
#else
#define ROTL(x, r) (((x) << (r)) | ((x) >> (32 - (r))))
#endif

// ---------------- Threefry-2x32 (20 rounds) --------------------------------
__host__ __device__ __forceinline__ void tf2x32(uint32_t k0, uint32_t k1,
                                                uint32_t x0, uint32_t x1,
                                                uint32_t &o0, uint32_t &o1)
{
    uint32_t ks2 = k0 ^ k1 ^ 0x1BD11BDAu;
    x0 += k0; x1 += k1;
#define TFR(r) { x0 += x1; x1 = ROTL(x1, r); x1 ^= x0; }
    TFR(13) TFR(15) TFR(26) TFR(6)
    x0 += k1;  x1 += ks2 + 1u;
    TFR(17) TFR(29) TFR(16) TFR(24)
    x0 += ks2; x1 += k0 + 2u;
    TFR(13) TFR(15) TFR(26) TFR(6)
    x0 += k0;  x1 += k1 + 3u;
    TFR(17) TFR(29) TFR(16) TFR(24)
    x0 += k1;  x1 += ks2 + 4u;
    TFR(13) TFR(15) TFR(26) TFR(6)
    x0 += ks2; x1 += k0 + 5u;
#undef TFR
    o0 = x0; o1 = x1;
}

// bit = (uniform(bits) < p)  ==  ((bits>>9) < ceil(p * 2^23))   (exact)
__device__ __forceinline__ uint32_t prob_to_int(float p)
{
    return (uint32_t)__float2int_ru(p * 8388608.0f);
}

// ---------------- merged bitgen: blocks [0,1024) -> A, [1024,1536) -> W -----
// A: (L,B,K), ctr = (l<<23)|(b<<11)|k ; W: (L,K,N), ctr = (l<<22)|(k<<11)|n
__global__ void __launch_bounds__(256) gen_bits(const float* __restrict__ x,
                                                const float* __restrict__ w,
                                                uint32_t a0, uint32_t a1,
                                                uint32_t b0, uint32_t b1)
{
    __shared__ int scnt[8];
    int t  = threadIdx.x;
    int kw = t & 63;
    bool isA = blockIdx.x < (B_DIM / 4);
    int rowblk = isA ? blockIdx.x : (blockIdx.x - B_DIM / 4);
    int row = rowblk * 4 + (t >> 6);

    const float* src = isA ? x : w;
    const float4* r4 = reinterpret_cast<const float4*>(
        src + (size_t)row * K_DIM + (size_t)kw * 32);
    uint32_t k0 = isA ? a0 : b0;
    uint32_t k1 = isA ? a1 : b1;

    uint32_t words[8] = {0,0,0,0,0,0,0,0};
#pragma unroll 2
    for (int jq = 0; jq < 8; ++jq) {
        float4 v4 = r4[jq];
        float vv[4] = {v4.x, v4.y, v4.z, v4.w};
#pragma unroll
        for (int jj = 0; jj < 4; ++jj) {
            int j = jq * 4 + jj;
            float p = fminf(fmaxf((vv[jj] + 1.0f) * 0.5f, 0.0f), 1.0f);
            uint32_t ip = prob_to_int(p);
            int kk = kw * 32 + j;
            uint32_t base = isA ? (((uint32_t)row << 11) | (uint32_t)kk)
                                : (((uint32_t)kk << 11) | (uint32_t)row);
            uint32_t lsh = isA ? 23 : 22;
#pragma unroll
            for (int l = 0; l < 8; ++l) {
                uint32_t o0, o1;
                tf2x32(k0, k1, 0u, ((uint32_t)l << lsh) | base, o0, o1);
                if (((o0 ^ o1) >> 9) < ip) words[l] |= (1u << j);
            }
        }
    }
    uint32_t* dst = isA ? g_Apack : g_Wpack;
    int cnt = 0;
#pragma unroll
    for (int l = 0; l < 8; ++l) {
        dst[(size_t)row * ROW_WORDS + l * 64 + kw] = words[l];
        cnt += __popc(words[l]);
    }
#pragma unroll
    for (int o = 16; o > 0; o >>= 1) cnt += __shfl_down_sync(0xffffffffu, cnt, o);
    if ((t & 31) == 0) scnt[t >> 5] = cnt;
    __syncthreads();
    if (t < 4) {
        int v = scnt[2 * t] + scnt[2 * t + 1];
        if (isA) g_sA[rowblk * 4 + t] = v;
        else     g_sB[rowblk * 4 + t] = v;
    }
}

// ---------------- popc GEMM (v10 core, int16 partial stores) -----------------
__device__ __forceinline__ uint32_t smem_u32(const void* p)
{
    uint32_t a;
    asm("{ .reg .u64 t; cvta.to.shared.u64 t, %1; cvt.u32.u64 %0, t; }" : "=r"(a) : "l"(p));
    return a;
}
__device__ __forceinline__ void cp16(uint32_t dst, const void* src)
{
    asm volatile("cp.async.cg.shared.global [%0], [%1], 16;" :: "r"(dst), "l"(src));
}
#define CP_COMMIT() asm volatile("cp.async.commit_group;" ::: "memory")
#define CP_WAIT2()  asm volatile("cp.async.wait_group 2;" ::: "memory")

__device__ __forceinline__ uint32_t xor3(uint32_t a, uint32_t b, uint32_t c)
{
    uint32_t r;
    asm("lop3.b32 %0, %1, %2, %3, 0x96;" : "=r"(r) : "r"(a), "r"(b), "r"(c));
    return r;
}
__device__ __forceinline__ uint32_t maj3(uint32_t a, uint32_t b, uint32_t c)
{
    uint32_t r;
    asm("lop3.b32 %0, %1, %2, %3, 0xE8;" : "=r"(r) : "r"(a), "r"(b), "r"(c));
    return r;
}

// CSA 7->3 + 1 naive over 8 AND-words: 4 POPC instead of 8.
__device__ __forceinline__ void csa8(int &acc,
                                     const uint4 &a0, const uint4 &a1,
                                     const uint4 &b0, const uint4 &b1)
{
    uint32_t x0 = a0.x & b0.x, x1 = a0.y & b0.y;
    uint32_t x2 = a0.z & b0.z, x3 = a0.w & b0.w;
    uint32_t x4 = a1.x & b1.x, x5 = a1.y & b1.y;
    uint32_t x6 = a1.z & b1.z, x7 = a1.w & b1.w;
    uint32_t s0 = xor3(x0, x1, x2), c0 = maj3(x0, x1, x2);
    uint32_t s1 = xor3(x3, x4, x5), c1 = maj3(x3, x4, x5);
    uint32_t S  = xor3(s0, s1, x6), c2 = maj3(s0, s1, x6);
    uint32_t C  = xor3(c0, c1, c2), CC = maj3(c0, c1, c2);
    acc += __popc(S) + __popc(x7)
         + 2 * __popc(C) + 4 * __popc(CC);
}

__device__ __forceinline__ uint4 lds128(uint32_t addr)
{
    uint4 v;
    asm volatile("ld.shared.v4.u32 {%0,%1,%2,%3}, [%4];"
                 : "=r"(v.x), "=r"(v.y), "=r"(v.z), "=r"(v.w) : "r"(addr));
    return v;
}

__global__ void __launch_bounds__(256, 2) popc_gemm14(void)
{
    extern __shared__ char smraw[];
    uint32_t sb = smem_u32(smraw);

    int tid = threadIdx.x;
    int tx  = tid & 15;        // 16 col-groups (cols tx + 16j, j=0..3)
    int ty  = tid >> 4;        // 16 row-groups (rows ty + 16i, i=0..7)
    int row0 = blockIdx.y * BM;
    int col0 = blockIdx.x * BN;
    int kt0  = blockIdx.z * NCHS;   // split-K offset (0 or 8)
    short* Sout = g_Sp[blockIdx.z];

    // stage loader: 1536 cp16 tasks (A: 1024, B: 512), 6 per thread
    auto load_stage = [&](int kt, int s) {
        uint32_t dst0 = sb + (uint32_t)s * STAGE_B;
#pragma unroll
        for (int q = 0; q < 6; ++q) {
            int task = tid + q * 256;          // 0..1535
            if (task < 1024) {
                int r = task >> 3, ch = task & 7;
                cp16(dst0 + (uint32_t)r * PITCH + (uint32_t)(ch << 4),
                     &g_Apack[(size_t)(row0 + r) * ROW_WORDS + kt * CW + ch * 4]);
            } else {
                int rem = task - 1024;
                int r = rem >> 3, ch = rem & 7;
                cp16(dst0 + A_TILE_B + (uint32_t)r * PITCH + (uint32_t)(ch << 4),
                     &g_Wpack[(size_t)(col0 + r) * ROW_WORDS + kt * CW + ch * 4]);
            }
        }
    };

    int acc[8][4];
#pragma unroll
    for (int i = 0; i < 8; ++i)
#pragma unroll
        for (int j = 0; j < 4; ++j) acc[i][j] = 0;

    load_stage(kt0 + 0, 0); CP_COMMIT();
    load_stage(kt0 + 1, 1); CP_COMMIT();
    load_stage(kt0 + 2, 2); CP_COMMIT();

    // 4-stage ring, distance-3 prefetch, ONE barrier per chunk.
    for (int t = 0; t < NCHS; ++t) {
        CP_WAIT2();
        __syncthreads();

        uint32_t base = sb + (uint32_t)(t & 3) * STAGE_B;
        uint32_t Ab = base + (uint32_t)ty * PITCH;
        uint32_t Bb = base + A_TILE_B + (uint32_t)tx * PITCH;

#pragma unroll 1
        for (int g = 0; g < 4; ++g) {           // 8 words = 32 B per row
            uint4 b0[4], b1[4];                  // B cols tx+16j, held over i
#pragma unroll
            for (int j = 0; j < 4; ++j) {
                uint32_t rb = Bb + j * (16 * PITCH) + g * 32;
                b0[j] = lds128(rb);
                b1[j] = lds128(rb + 16);
            }
#pragma unroll
            for (int ih = 0; ih < 2; ++ih) {     // i in halves of 4 (regs)
                uint4 a0[4], a1[4];
#pragma unroll
                for (int i4 = 0; i4 < 4; ++i4) {
                    uint32_t rb = Ab + (ih * 4 + i4) * (16 * PITCH) + g * 32;
                    a0[i4] = lds128(rb);
                    a1[i4] = lds128(rb + 16);
                }
#pragma unroll
                for (int i4 = 0; i4 < 4; ++i4)
#pragma unroll
                    for (int j = 0; j < 4; ++j)
                        csa8(acc[ih * 4 + i4][j], a0[i4], a1[i4], b0[j], b1[j]);
            }
        }
        if (t + 3 < NCHS) load_stage(kt0 + t + 3, (t + 3) & 3);
        CP_COMMIT();   // commit every iter (possibly empty) keeps counts aligned
    }

    // write partial S (int16, max 8192: exact) with plain stores
#pragma unroll
    for (int i = 0; i < 8; ++i) {
        int row = row0 + ty + 16 * i;
#pragma unroll
        for (int j = 0; j < 4; ++j) {
            int col = col0 + tx + 16 * j;
            Sout[(size_t)row * N_DIM + col] = (short)acc[i][j];
        }
    }
}

// ---------------- exact epilogue: 8 cols/thread -----------------------------
__global__ void __launch_bounds__(256) ep_out8(const float* __restrict__ bias,
                                               float* __restrict__ out)
{
    int idx = blockIdx.x * 256 + threadIdx.x;      // 512K threads, 8 cols each
    int row = idx >> 8;
    int c8  = (idx & 255) * 8;
    float sa = (float)__ldg(&g_sA[row]);

    const short* p0 = &g_Sp[0][(size_t)row * N_DIM + c8];
    const short* p1 = &g_Sp[1][(size_t)row * N_DIM + c8];
    short s0[8], s1[8];
    *reinterpret_cast<uint4*>(s0) = *reinterpret_cast<const uint4*>(p0);
    *reinterpret_cast<uint4*>(s1) = *reinterpret_cast<const uint4*>(p1);

    float* orow = &out[(size_t)row * N_DIM + c8];
#pragma unroll
    for (int h = 0; h < 2; ++h) {
        float4 bv = *reinterpret_cast<const float4*>(&bias[c8 + 4 * h]);
        int4 sbv  = *reinterpret_cast<const int4*>(&g_sB[c8 + 4 * h]);
        float4 ov;
        ov.x = 0.5f * (float)(s0[4*h+0] + s1[4*h+0]) - 0.25f * (sa + (float)sbv.x) + 2048.0f + bv.x;
        ov.y = 0.5f * (float)(s0[4*h+1] + s1[4*h+1]) - 0.25f * (sa + (float)sbv.y) + 2048.0f + bv.y;
        ov.z = 0.5f * (float)(s0[4*h+2] + s1[4*h+2]) - 0.25f * (sa + (float)sbv.z) + 2048.0f + bv.z;
        ov.w = 0.5f * (float)(s0[4*h+3] + s1[4*h+3]) - 0.25f * (sa + (float)sbv.w) + 2048.0f + bv.w;
        *reinterpret_cast<float4*>(&orow[4 * h]) = ov;
    }
}

// ---------------------------------------------------------------------------
extern "C" void kernel_launch(void* const* d_in, const int* in_sizes, int n_in,
                              void* d_out, int out_size)
{
    const float* x    = (const float*)d_in[0];
    const float* w    = (const float*)d_in[1];
    const float* bias = (const float*)d_in[2];
    float* out        = (float*)d_out;

    // jax.random.split(jax.random.key(42)), partitionable (foldlike)
    uint32_t kA0, kA1, kB0, kB1;
    tf2x32(0u, 42u, 0u, 0u, kA0, kA1);
    tf2x32(0u, 42u, 0u, 1u, kB0, kB1);

    cudaFuncSetAttribute(popc_gemm14,
                         cudaFuncAttributeMaxDynamicSharedMemorySize, SMEM_BYTES);

    gen_bits<<<(B_DIM + N_DIM) / 4, 256>>>(x, w, kA0, kA1, kB0, kB1);
    popc_gemm14<<<dim3(N_DIM / BN, B_DIM / BM, KSPLIT), 256, SMEM_BYTES>>>();
    ep_out8<<<(B_DIM * N_DIM / 8) / 256, 256>>>(bias, out);
}